// round 11
// baseline (speedup 1.0000x reference)
#include <cuda_runtime.h>
#include <cuda_bf16.h>
#include <math.h>
#include <stdint.h>

// Problem constants
#define BB 1024   // batch (edges per direction)
#define NN 1024   // nodes
#define DD 256    // feature dim
#define K3 768    // 3*D

// ---------------- static scratch (no allocations allowed) ----------------
__device__ __nv_bfloat16 g_Xh[2 * BB * K3], g_Xl[2 * BB * K3];   // MLP inputs hi/lo
__device__ __nv_bfloat16 g_Hh[2 * BB * DD], g_Hl[2 * BB * DD];   // hidden hi/lo
__device__ float         g_MSG[2 * BB * DD];                     // messages fp32
__device__ __nv_bfloat16 g_AGGh[NN * DD], g_AGGl[NN * DD];       // segment mean hi/lo
__device__ float         g_G[2 * NN * K3];                       // gi | gh fp32
__device__ int           g_CNT[NN];

// ---------------- fp32 -> bf16 hi/lo split ----------------
__device__ __forceinline__ void split_bf16(float v, __nv_bfloat16& h, __nv_bfloat16& l) {
    h = __float2bfloat16(v);
    l = __float2bfloat16(v - __bfloat162float(h));
}
__device__ __forceinline__ uint32_t pack2(__nv_bfloat16 a, __nv_bfloat16 b) {
    __nv_bfloat162 t; t.x = a; t.y = b;
    return *reinterpret_cast<uint32_t*>(&t);
}

// ---------------- gather: build concat inputs (bf16 hi/lo) ----------------
__global__ void gather_kernel(const float* __restrict__ memory,
                              const int* __restrict__ src,
                              const int* __restrict__ tgt,
                              const float* __restrict__ dtv) {
    int b = blockIdx.x;
    int d = threadIdx.x;
    int s = src[b];
    int t = tgt[b];
    float ms = memory[(size_t)s * DD + d];
    float mt = memory[(size_t)t * DD + d];
    float ds = dtv[((size_t)b * NN + s) * DD + d];
    float dt = dtv[((size_t)b * NN + t) * DD + d];
    size_t rs = (size_t)b * K3;
    size_t rt = (size_t)(BB + b) * K3;
    __nv_bfloat16 h, l;
    split_bf16(ms, h, l); g_Xh[rs + d] = h;          g_Xl[rs + d] = l;
    split_bf16(mt, h, l); g_Xh[rs + DD + d] = h;     g_Xl[rs + DD + d] = l;
    split_bf16(ds, h, l); g_Xh[rs + 2*DD + d] = h;   g_Xl[rs + 2*DD + d] = l;
    split_bf16(mt, h, l); g_Xh[rt + d] = h;          g_Xl[rt + d] = l;
    split_bf16(ms, h, l); g_Xh[rt + DD + d] = h;     g_Xl[rt + DD + d] = l;
    split_bf16(dt, h, l); g_Xh[rt + 2*DD + d] = h;   g_Xl[rt + 2*DD + d] = l;
}

// ---------------- mma.sync bf16 helper ----------------
__device__ __forceinline__ void mma_bf16(float* c, const uint32_t* a, const uint32_t* b) {
    asm volatile(
        "mma.sync.aligned.m16n8k16.row.col.f32.bf16.bf16.f32 "
        "{%0,%1,%2,%3}, {%4,%5,%6,%7}, {%8,%9}, {%0,%1,%2,%3};\n"
        : "+f"(c[0]), "+f"(c[1]), "+f"(c[2]), "+f"(c[3])
        : "r"(a[0]), "r"(a[1]), "r"(a[2]), "r"(a[3]), "r"(b[0]), "r"(b[1]));
}

// ---------------- tensor-core dual-half GEMM (mma.sync, 3-term bf16 split) ----
// Register-pipelined staging: LDGs for chunk c+1 issue before compute of chunk c.
#define SPAD 40

union LoadRegs {
    struct { uint4 vh, vl; } bf;
    struct { float4 f0, f1; } fp;
};

__device__ __forceinline__ void load_regs(
    LoadRegs& r,
    const __nv_bfloat16* __restrict__ gh, const __nv_bfloat16* __restrict__ gl,
    const float* __restrict__ gf,
    int grow0, int ld, int kt, int lr, int lk) {
    if (gf) {
        const float* p = &gf[(size_t)(grow0 + lr) * ld + kt + lk];
        r.fp.f0 = *reinterpret_cast<const float4*>(p);
        r.fp.f1 = *reinterpret_cast<const float4*>(p + 4);
    } else {
        r.bf.vh = *reinterpret_cast<const uint4*>(&gh[(size_t)(grow0 + lr) * ld + kt + lk]);
        r.bf.vl = *reinterpret_cast<const uint4*>(&gl[(size_t)(grow0 + lr) * ld + kt + lk]);
    }
}

__device__ __forceinline__ void store_regs(
    __nv_bfloat16* sh, __nv_bfloat16* sl, const LoadRegs& r,
    bool isFp, int lr, int lk) {
    if (isFp) {
        __nv_bfloat16 h0,l0,h1,l1,h2,l2,h3,l3,h4,l4,h5,l5,h6,l6,h7,l7;
        split_bf16(r.fp.f0.x, h0, l0); split_bf16(r.fp.f0.y, h1, l1);
        split_bf16(r.fp.f0.z, h2, l2); split_bf16(r.fp.f0.w, h3, l3);
        split_bf16(r.fp.f1.x, h4, l4); split_bf16(r.fp.f1.y, h5, l5);
        split_bf16(r.fp.f1.z, h6, l6); split_bf16(r.fp.f1.w, h7, l7);
        uint4 vh = make_uint4(pack2(h0,h1), pack2(h2,h3), pack2(h4,h5), pack2(h6,h7));
        uint4 vl = make_uint4(pack2(l0,l1), pack2(l2,l3), pack2(l4,l5), pack2(l6,l7));
        *reinterpret_cast<uint4*>(&sh[lr * SPAD + lk]) = vh;
        *reinterpret_cast<uint4*>(&sl[lr * SPAD + lk]) = vl;
    } else {
        *reinterpret_cast<uint4*>(&sh[lr * SPAD + lk]) = r.bf.vh;
        *reinterpret_cast<uint4*>(&sl[lr * SPAD + lk]) = r.bf.vl;
    }
}

__global__ __launch_bounds__(256) void tgemm_kernel(
    const __nv_bfloat16* __restrict__ Ah0, const __nv_bfloat16* __restrict__ Al0,
    const float* __restrict__ Af0,
    const __nv_bfloat16* __restrict__ Ah1, const __nv_bfloat16* __restrict__ Al1,
    const float* __restrict__ Af1,
    const float* __restrict__ Wf0, const float* __restrict__ Wf1,
    const float* __restrict__ b0, const float* __restrict__ b1,
    float* __restrict__ Cf, __nv_bfloat16* __restrict__ Chi, __nv_bfloat16* __restrict__ Clo,
    int halfM, int Nn, int Kk, int doRelu) {

    __shared__ __align__(16) __nv_bfloat16 sAh[64 * SPAD];
    __shared__ __align__(16) __nv_bfloat16 sAl[64 * SPAD];
    __shared__ __align__(16) __nv_bfloat16 sWh[64 * SPAD];
    __shared__ __align__(16) __nv_bfloat16 sWl[64 * SPAD];

    const int tid  = threadIdx.x;
    const int wid  = tid >> 5;
    const int lane = tid & 31;
    const int gid  = lane >> 2;   // 0..7
    const int tig  = lane & 3;    // 0..3

    const int row0 = blockIdx.y * 64;
    const int col0 = blockIdx.x * 64;
    const bool hi2 = (row0 >= halfM);
    const __nv_bfloat16* __restrict__ Ah = hi2 ? Ah1 : Ah0;
    const __nv_bfloat16* __restrict__ Al = hi2 ? Al1 : Al0;
    const float* __restrict__ Af = hi2 ? Af1 : Af0;
    const float* __restrict__ Wf = hi2 ? Wf1 : Wf0;
    const float* __restrict__ bias = hi2 ? b1 : b0;
    const int arow0 = row0 - (hi2 ? halfM : 0);
    const bool aFp = (Af != nullptr);

    const int warp_m = wid >> 2;  // 0..1
    const int warp_n = wid & 3;   // 0..3

    float acc[2][2][4];
#pragma unroll
    for (int mi = 0; mi < 2; mi++)
#pragma unroll
        for (int ni = 0; ni < 2; ni++)
#pragma unroll
            for (int j = 0; j < 4; j++) acc[mi][ni][j] = 0.0f;

    const int lr = tid >> 2;          // load row 0..63
    const int lk = (tid & 3) * 8;     // load k offset 0,8,16,24

    const int NC = Kk >> 5;
    LoadRegs ra, rw;
    load_regs(ra, Ah, Al, Af, arow0, Kk, 0, lr, lk);
    load_regs(rw, nullptr, nullptr, Wf, col0, Kk, 0, lr, lk);

    for (int c = 0; c < NC; c++) {
        store_regs(sAh, sAl, ra, aFp, lr, lk);
        store_regs(sWh, sWl, rw, true, lr, lk);
        __syncthreads();

        if (c + 1 < NC) {
            const int kt = (c + 1) * 32;
            load_regs(ra, Ah, Al, Af, arow0, Kk, kt, lr, lk);
            load_regs(rw, nullptr, nullptr, Wf, col0, Kk, kt, lr, lk);
        }

#pragma unroll
        for (int ks = 0; ks < 2; ks++) {
            const int kk = ks * 16 + tig * 2;
            uint32_t ah[2][4], al[2][4];
#pragma unroll
            for (int mi = 0; mi < 2; mi++) {
                const int rb = warp_m * 32 + mi * 16;
                ah[mi][0] = *reinterpret_cast<const uint32_t*>(&sAh[(rb + gid) * SPAD + kk]);
                ah[mi][1] = *reinterpret_cast<const uint32_t*>(&sAh[(rb + gid + 8) * SPAD + kk]);
                ah[mi][2] = *reinterpret_cast<const uint32_t*>(&sAh[(rb + gid) * SPAD + kk + 8]);
                ah[mi][3] = *reinterpret_cast<const uint32_t*>(&sAh[(rb + gid + 8) * SPAD + kk + 8]);
                al[mi][0] = *reinterpret_cast<const uint32_t*>(&sAl[(rb + gid) * SPAD + kk]);
                al[mi][1] = *reinterpret_cast<const uint32_t*>(&sAl[(rb + gid + 8) * SPAD + kk]);
                al[mi][2] = *reinterpret_cast<const uint32_t*>(&sAl[(rb + gid) * SPAD + kk + 8]);
                al[mi][3] = *reinterpret_cast<const uint32_t*>(&sAl[(rb + gid + 8) * SPAD + kk + 8]);
            }
            uint32_t bh[2][2], bl[2][2];
#pragma unroll
            for (int ni = 0; ni < 2; ni++) {
                const int nr = warp_n * 16 + ni * 8 + gid;
                bh[ni][0] = *reinterpret_cast<const uint32_t*>(&sWh[nr * SPAD + kk]);
                bh[ni][1] = *reinterpret_cast<const uint32_t*>(&sWh[nr * SPAD + kk + 8]);
                bl[ni][0] = *reinterpret_cast<const uint32_t*>(&sWl[nr * SPAD + kk]);
                bl[ni][1] = *reinterpret_cast<const uint32_t*>(&sWl[nr * SPAD + kk + 8]);
            }
#pragma unroll
            for (int mi = 0; mi < 2; mi++)
#pragma unroll
                for (int ni = 0; ni < 2; ni++) {
                    mma_bf16(acc[mi][ni], ah[mi], bh[ni]);
                    mma_bf16(acc[mi][ni], ah[mi], bl[ni]);
                    mma_bf16(acc[mi][ni], al[mi], bh[ni]);
                }
        }
        __syncthreads();
    }

    // ---- epilogue: bias + activation + stores ----
#pragma unroll
    for (int mi = 0; mi < 2; mi++) {
#pragma unroll
        for (int ni = 0; ni < 2; ni++) {
            const int r0 = row0 + warp_m * 32 + mi * 16 + gid;
            const int c  = col0 + warp_n * 16 + ni * 8 + tig * 2;
            const float bx = bias[c];
            const float by = bias[c + 1];
            float v0 = acc[mi][ni][0] + bx;
            float v1 = acc[mi][ni][1] + by;
            float v2 = acc[mi][ni][2] + bx;
            float v3 = acc[mi][ni][3] + by;
            if (doRelu) {
                v0 = fmaxf(v0, 0.0f); v1 = fmaxf(v1, 0.0f);
                v2 = fmaxf(v2, 0.0f); v3 = fmaxf(v3, 0.0f);
            }
            if (Cf) {
                *reinterpret_cast<float2*>(&Cf[(size_t)r0 * Nn + c])       = make_float2(v0, v1);
                *reinterpret_cast<float2*>(&Cf[(size_t)(r0 + 8) * Nn + c]) = make_float2(v2, v3);
            }
            if (Chi) {
                __nv_bfloat16 h0, l0, h1, l1;
                split_bf16(v0, h0, l0); split_bf16(v1, h1, l1);
                *reinterpret_cast<uint32_t*>(&Chi[(size_t)r0 * Nn + c]) = pack2(h0, h1);
                *reinterpret_cast<uint32_t*>(&Clo[(size_t)r0 * Nn + c]) = pack2(l0, l1);
                split_bf16(v2, h0, l0); split_bf16(v3, h1, l1);
                *reinterpret_cast<uint32_t*>(&Chi[(size_t)(r0 + 8) * Nn + c]) = pack2(h0, h1);
                *reinterpret_cast<uint32_t*>(&Clo[(size_t)(r0 + 8) * Nn + c]) = pack2(l0, l1);
            }
        }
    }
}

// ---------------- deterministic segment mean (4 nodes/block, capped lists) ----
// Stage all 2048 edge ids once per block; 8 warps scan 256-edge chunks and
// match 4 nodes per staged value. Ordered per-node edge lists are CAPPED at
// SEG_CAP entries (expected count ~2); any overflowing node takes a correct
// slow path that rescans the staged ids in ascending edge order. smem ~11KB
// keeps occupancy high (the 41KB version tanked occ to 20%).
#define NPB 4
#define SEG_CAP 160
__global__ __launch_bounds__(256) void segment_kernel(const int* __restrict__ src,
                                                      const int* __restrict__ tgt) {
    __shared__ int s_ids[2 * BB];
    __shared__ int s_list[NPB][SEG_CAP];
    __shared__ int s_wbase[NPB][8];
    __shared__ int s_total[NPB];
    const int n0  = blockIdx.x * NPB;
    const int tid = threadIdx.x;
    const int wid = tid >> 5;
    const int lid = tid & 31;

#pragma unroll
    for (int i = 0; i < 8; i++) {
        int e = tid + i * 256;
        s_ids[e] = (e < BB) ? src[e] : tgt[e - BB];
    }
    __syncthreads();

    const int chunk0 = wid * 256;

    // pass 1: per-warp match counts for all 4 nodes
    int cnt[NPB] = {0, 0, 0, 0};
#pragma unroll
    for (int r = 0; r < 8; r++) {
        int v = s_ids[chunk0 + r * 32 + lid];
#pragma unroll
        for (int j = 0; j < NPB; j++) {
            unsigned m = __ballot_sync(0xffffffffu, v == n0 + j);
            cnt[j] += __popc(m);
        }
    }
    if (lid == 0) {
#pragma unroll
        for (int j = 0; j < NPB; j++) s_wbase[j][wid] = cnt[j];
    }
    __syncthreads();

    if (tid < NPB) {
        int acc = 0;
#pragma unroll
        for (int w = 0; w < 8; w++) { int c = s_wbase[tid][w]; s_wbase[tid][w] = acc; acc += c; }
        s_total[tid] = acc;
    }
    __syncthreads();

    // pass 2: write ordered edge lists (bounded by SEG_CAP)
    int base[NPB];
#pragma unroll
    for (int j = 0; j < NPB; j++) base[j] = s_wbase[j][wid];
#pragma unroll
    for (int r = 0; r < 8; r++) {
        int e = chunk0 + r * 32 + lid;
        int v = s_ids[e];
#pragma unroll
        for (int j = 0; j < NPB; j++) {
            bool hit = (v == n0 + j);
            unsigned m = __ballot_sync(0xffffffffu, hit);
            if (hit) {
                int pos = base[j] + __popc(m & ((1u << lid) - 1u));
                if (pos < SEG_CAP) s_list[j][pos] = e;
            }
            base[j] += __popc(m);
        }
    }
    __syncthreads();

    // reductions (ascending edge order per node)
#pragma unroll 1
    for (int j = 0; j < NPB; j++) {
        const int n = n0 + j;
        const int total = s_total[j];
        float sum = 0.0f;
        if (total <= SEG_CAP) {
            for (int i = 0; i < total; i++) {
                int e = s_list[j][i];
                sum += g_MSG[(size_t)e * DD + tid];
            }
        } else {
            // slow path (never expected): rescan staged ids in ascending order
            for (int e = 0; e < 2 * BB; e++) {
                if (s_ids[e] == n) sum += g_MSG[(size_t)e * DD + tid];
            }
        }
        float denom = (total > 0) ? (float)total : 1.0f;
        float mean = sum / denom;
        __nv_bfloat16 h, l;
        split_bf16(mean, h, l);
        g_AGGh[(size_t)n * DD + tid] = h;
        g_AGGl[(size_t)n * DD + tid] = l;
        if (tid == 0) g_CNT[n] = total;
    }
}

// ---------------- GRU gates + masked write ----------------
__global__ void gate_kernel(const float* __restrict__ memory,
                            float* __restrict__ out) {
    const int n = blockIdx.x;
    const int d = threadIdx.x;
    const float* gi = g_G + (size_t)n * K3;
    const float* gh = g_G + (size_t)(NN + n) * K3;

    float r  = 1.0f / (1.0f + expf(-(gi[d] + gh[d])));
    float z  = 1.0f / (1.0f + expf(-(gi[DD + d] + gh[DD + d])));
    float nn = tanhf(gi[2 * DD + d] + r * gh[2 * DD + d]);
    float h  = memory[(size_t)n * DD + d];
    float nv = (1.0f - z) * nn + z * h;
    out[(size_t)n * DD + d] = (g_CNT[n] > 0) ? nv : h;
}

// ---------------- launch ----------------
extern "C" void kernel_launch(void* const* d_in, const int* in_sizes, int n_in,
                              void* d_out, int out_size) {
    const float* memory  = (const float*)d_in[0];
    const int*   source  = (const int*)d_in[1];
    const int*   target  = (const int*)d_in[2];
    const float* dtv     = (const float*)d_in[3];
    const float* src_w1  = (const float*)d_in[4];
    const float* src_b1  = (const float*)d_in[5];
    const float* src_w2  = (const float*)d_in[6];
    const float* src_b2  = (const float*)d_in[7];
    const float* tar_w1  = (const float*)d_in[8];
    const float* tar_b1  = (const float*)d_in[9];
    const float* tar_w2  = (const float*)d_in[10];
    const float* tar_b2  = (const float*)d_in[11];
    const float* gru_wih = (const float*)d_in[12];
    const float* gru_whh = (const float*)d_in[13];
    const float* gru_bih = (const float*)d_in[14];
    const float* gru_bhh = (const float*)d_in[15];
    float* out = (float*)d_out;

    __nv_bfloat16 *pXh, *pXl, *pHh, *pHl, *pAGGh, *pAGGl;
    float *pMSG, *pG;
    cudaGetSymbolAddress((void**)&pXh, g_Xh);   cudaGetSymbolAddress((void**)&pXl, g_Xl);
    cudaGetSymbolAddress((void**)&pHh, g_Hh);   cudaGetSymbolAddress((void**)&pHl, g_Hl);
    cudaGetSymbolAddress((void**)&pAGGh, g_AGGh); cudaGetSymbolAddress((void**)&pAGGl, g_AGGl);
    cudaGetSymbolAddress((void**)&pMSG, g_MSG); cudaGetSymbolAddress((void**)&pG, g_G);

    // 1) gather concat inputs (bf16 hi/lo)
    gather_kernel<<<BB, DD>>>(memory, source, target, dtv);

    // 2) MLP layer 1 (relu): X[2048,768] -> H[2048,256] (bf16 hi/lo out)
    tgemm_kernel<<<dim3(DD / 64, (2 * BB) / 64), 256>>>(
        pXh, pXl, nullptr,
        pXh + (size_t)BB * K3, pXl + (size_t)BB * K3, nullptr,
        src_w1, tar_w1,
        src_b1, tar_b1, nullptr, pHh, pHl, BB, DD, K3, 1);

    // 3) MLP layer 2: H[2048,256] -> MSG[2048,256] fp32
    tgemm_kernel<<<dim3(DD / 64, (2 * BB) / 64), 256>>>(
        pHh, pHl, nullptr,
        pHh + (size_t)BB * DD, pHl + (size_t)BB * DD, nullptr,
        src_w2, tar_w2,
        src_b2, tar_b2, pMSG, nullptr, nullptr, BB, DD, DD, 0);

    // 4) deterministic segment mean -> AGG hi/lo, CNT (4 nodes/block, capped lists)
    segment_kernel<<<NN / NPB, 256>>>(source, target);

    // 5) GRU preactivations: gi = agg@wih^T + bih ; gh = memory@whh^T + bhh
    tgemm_kernel<<<dim3(K3 / 64, (2 * NN) / 64), 256>>>(
        pAGGh, pAGGl, nullptr,
        nullptr, nullptr, memory,
        gru_wih, gru_whh,
        gru_bih, gru_bhh, pG, nullptr, nullptr, NN, K3, DD, 0);

    // 6) gates + masked output
    gate_kernel<<<NN, DD>>>(memory, out);
}

// round 12
// speedup vs baseline: 1.5310x; 1.5310x over previous
#include <cuda_runtime.h>
#include <cuda_bf16.h>
#include <math.h>
#include <stdint.h>

// Problem constants
#define BB 1024   // batch (edges per direction)
#define NN 1024   // nodes
#define DD 256    // feature dim
#define K3 768    // 3*D

// ---------------- static scratch (no allocations allowed) ----------------
__device__ __nv_bfloat16 g_Xh[2 * BB * K3], g_Xl[2 * BB * K3];   // MLP inputs hi/lo
__device__ __nv_bfloat16 g_Hh[2 * BB * DD], g_Hl[2 * BB * DD];   // hidden hi/lo
__device__ float         g_MSG[2 * BB * DD];                     // messages fp32
__device__ __nv_bfloat16 g_AGGh[NN * DD], g_AGGl[NN * DD];       // segment mean hi/lo
__device__ float         g_G[2 * NN * K3];                       // gi | gh fp32
__device__ int           g_CNT[NN];

// ---------------- fp32 -> bf16 hi/lo split ----------------
__device__ __forceinline__ void split_bf16(float v, __nv_bfloat16& h, __nv_bfloat16& l) {
    h = __float2bfloat16(v);
    l = __float2bfloat16(v - __bfloat162float(h));
}
__device__ __forceinline__ uint32_t pack2(__nv_bfloat16 a, __nv_bfloat16 b) {
    __nv_bfloat162 t; t.x = a; t.y = b;
    return *reinterpret_cast<uint32_t*>(&t);
}

// ---------------- gather: build concat inputs (bf16 hi/lo) ----------------
__global__ void gather_kernel(const float* __restrict__ memory,
                              const int* __restrict__ src,
                              const int* __restrict__ tgt,
                              const float* __restrict__ dtv) {
    int b = blockIdx.x;
    int d = threadIdx.x;
    int s = src[b];
    int t = tgt[b];
    float ms = memory[(size_t)s * DD + d];
    float mt = memory[(size_t)t * DD + d];
    float ds = dtv[((size_t)b * NN + s) * DD + d];
    float dt = dtv[((size_t)b * NN + t) * DD + d];
    size_t rs = (size_t)b * K3;
    size_t rt = (size_t)(BB + b) * K3;
    __nv_bfloat16 h, l;
    split_bf16(ms, h, l); g_Xh[rs + d] = h;          g_Xl[rs + d] = l;
    split_bf16(mt, h, l); g_Xh[rs + DD + d] = h;     g_Xl[rs + DD + d] = l;
    split_bf16(ds, h, l); g_Xh[rs + 2*DD + d] = h;   g_Xl[rs + 2*DD + d] = l;
    split_bf16(mt, h, l); g_Xh[rt + d] = h;          g_Xl[rt + d] = l;
    split_bf16(ms, h, l); g_Xh[rt + DD + d] = h;     g_Xl[rt + DD + d] = l;
    split_bf16(dt, h, l); g_Xh[rt + 2*DD + d] = h;   g_Xl[rt + 2*DD + d] = l;
}

// ---------------- mma.sync bf16 helper ----------------
__device__ __forceinline__ void mma_bf16(float* c, const uint32_t* a, const uint32_t* b) {
    asm volatile(
        "mma.sync.aligned.m16n8k16.row.col.f32.bf16.bf16.f32 "
        "{%0,%1,%2,%3}, {%4,%5,%6,%7}, {%8,%9}, {%0,%1,%2,%3};\n"
        : "+f"(c[0]), "+f"(c[1]), "+f"(c[2]), "+f"(c[3])
        : "r"(a[0]), "r"(a[1]), "r"(a[2]), "r"(a[3]), "r"(b[0]), "r"(b[1]));
}

// ---------------- tensor-core dual-half GEMM (mma.sync, 3-term bf16 split) ----
// Register-pipelined staging: LDGs for chunk c+1 issue before compute of chunk c.
#define SPAD 40

union LoadRegs {
    struct { uint4 vh, vl; } bf;
    struct { float4 f0, f1; } fp;
};

__device__ __forceinline__ void load_regs(
    LoadRegs& r,
    const __nv_bfloat16* __restrict__ gh, const __nv_bfloat16* __restrict__ gl,
    const float* __restrict__ gf,
    int grow0, int ld, int kt, int lr, int lk) {
    if (gf) {
        const float* p = &gf[(size_t)(grow0 + lr) * ld + kt + lk];
        r.fp.f0 = *reinterpret_cast<const float4*>(p);
        r.fp.f1 = *reinterpret_cast<const float4*>(p + 4);
    } else {
        r.bf.vh = *reinterpret_cast<const uint4*>(&gh[(size_t)(grow0 + lr) * ld + kt + lk]);
        r.bf.vl = *reinterpret_cast<const uint4*>(&gl[(size_t)(grow0 + lr) * ld + kt + lk]);
    }
}

__device__ __forceinline__ void store_regs(
    __nv_bfloat16* sh, __nv_bfloat16* sl, const LoadRegs& r,
    bool isFp, int lr, int lk) {
    if (isFp) {
        __nv_bfloat16 h0,l0,h1,l1,h2,l2,h3,l3,h4,l4,h5,l5,h6,l6,h7,l7;
        split_bf16(r.fp.f0.x, h0, l0); split_bf16(r.fp.f0.y, h1, l1);
        split_bf16(r.fp.f0.z, h2, l2); split_bf16(r.fp.f0.w, h3, l3);
        split_bf16(r.fp.f1.x, h4, l4); split_bf16(r.fp.f1.y, h5, l5);
        split_bf16(r.fp.f1.z, h6, l6); split_bf16(r.fp.f1.w, h7, l7);
        uint4 vh = make_uint4(pack2(h0,h1), pack2(h2,h3), pack2(h4,h5), pack2(h6,h7));
        uint4 vl = make_uint4(pack2(l0,l1), pack2(l2,l3), pack2(l4,l5), pack2(l6,l7));
        *reinterpret_cast<uint4*>(&sh[lr * SPAD + lk]) = vh;
        *reinterpret_cast<uint4*>(&sl[lr * SPAD + lk]) = vl;
    } else {
        *reinterpret_cast<uint4*>(&sh[lr * SPAD + lk]) = r.bf.vh;
        *reinterpret_cast<uint4*>(&sl[lr * SPAD + lk]) = r.bf.vl;
    }
}

__global__ __launch_bounds__(256) void tgemm_kernel(
    const __nv_bfloat16* __restrict__ Ah0, const __nv_bfloat16* __restrict__ Al0,
    const float* __restrict__ Af0,
    const __nv_bfloat16* __restrict__ Ah1, const __nv_bfloat16* __restrict__ Al1,
    const float* __restrict__ Af1,
    const float* __restrict__ Wf0, const float* __restrict__ Wf1,
    const float* __restrict__ b0, const float* __restrict__ b1,
    float* __restrict__ Cf, __nv_bfloat16* __restrict__ Chi, __nv_bfloat16* __restrict__ Clo,
    int halfM, int Nn, int Kk, int doRelu) {

    __shared__ __align__(16) __nv_bfloat16 sAh[64 * SPAD];
    __shared__ __align__(16) __nv_bfloat16 sAl[64 * SPAD];
    __shared__ __align__(16) __nv_bfloat16 sWh[64 * SPAD];
    __shared__ __align__(16) __nv_bfloat16 sWl[64 * SPAD];

    const int tid  = threadIdx.x;
    const int wid  = tid >> 5;
    const int lane = tid & 31;
    const int gid  = lane >> 2;   // 0..7
    const int tig  = lane & 3;    // 0..3

    const int row0 = blockIdx.y * 64;
    const int col0 = blockIdx.x * 64;
    const bool hi2 = (row0 >= halfM);
    const __nv_bfloat16* __restrict__ Ah = hi2 ? Ah1 : Ah0;
    const __nv_bfloat16* __restrict__ Al = hi2 ? Al1 : Al0;
    const float* __restrict__ Af = hi2 ? Af1 : Af0;
    const float* __restrict__ Wf = hi2 ? Wf1 : Wf0;
    const float* __restrict__ bias = hi2 ? b1 : b0;
    const int arow0 = row0 - (hi2 ? halfM : 0);
    const bool aFp = (Af != nullptr);

    const int warp_m = wid >> 2;  // 0..1
    const int warp_n = wid & 3;   // 0..3

    float acc[2][2][4];
#pragma unroll
    for (int mi = 0; mi < 2; mi++)
#pragma unroll
        for (int ni = 0; ni < 2; ni++)
#pragma unroll
            for (int j = 0; j < 4; j++) acc[mi][ni][j] = 0.0f;

    const int lr = tid >> 2;          // load row 0..63
    const int lk = (tid & 3) * 8;     // load k offset 0,8,16,24

    const int NC = Kk >> 5;
    LoadRegs ra, rw;
    load_regs(ra, Ah, Al, Af, arow0, Kk, 0, lr, lk);
    load_regs(rw, nullptr, nullptr, Wf, col0, Kk, 0, lr, lk);

    for (int c = 0; c < NC; c++) {
        store_regs(sAh, sAl, ra, aFp, lr, lk);
        store_regs(sWh, sWl, rw, true, lr, lk);
        __syncthreads();

        if (c + 1 < NC) {
            const int kt = (c + 1) * 32;
            load_regs(ra, Ah, Al, Af, arow0, Kk, kt, lr, lk);
            load_regs(rw, nullptr, nullptr, Wf, col0, Kk, kt, lr, lk);
        }

#pragma unroll
        for (int ks = 0; ks < 2; ks++) {
            const int kk = ks * 16 + tig * 2;
            uint32_t ah[2][4], al[2][4];
#pragma unroll
            for (int mi = 0; mi < 2; mi++) {
                const int rb = warp_m * 32 + mi * 16;
                ah[mi][0] = *reinterpret_cast<const uint32_t*>(&sAh[(rb + gid) * SPAD + kk]);
                ah[mi][1] = *reinterpret_cast<const uint32_t*>(&sAh[(rb + gid + 8) * SPAD + kk]);
                ah[mi][2] = *reinterpret_cast<const uint32_t*>(&sAh[(rb + gid) * SPAD + kk + 8]);
                ah[mi][3] = *reinterpret_cast<const uint32_t*>(&sAh[(rb + gid + 8) * SPAD + kk + 8]);
                al[mi][0] = *reinterpret_cast<const uint32_t*>(&sAl[(rb + gid) * SPAD + kk]);
                al[mi][1] = *reinterpret_cast<const uint32_t*>(&sAl[(rb + gid + 8) * SPAD + kk]);
                al[mi][2] = *reinterpret_cast<const uint32_t*>(&sAl[(rb + gid) * SPAD + kk + 8]);
                al[mi][3] = *reinterpret_cast<const uint32_t*>(&sAl[(rb + gid + 8) * SPAD + kk + 8]);
            }
            uint32_t bh[2][2], bl[2][2];
#pragma unroll
            for (int ni = 0; ni < 2; ni++) {
                const int nr = warp_n * 16 + ni * 8 + gid;
                bh[ni][0] = *reinterpret_cast<const uint32_t*>(&sWh[nr * SPAD + kk]);
                bh[ni][1] = *reinterpret_cast<const uint32_t*>(&sWh[nr * SPAD + kk + 8]);
                bl[ni][0] = *reinterpret_cast<const uint32_t*>(&sWl[nr * SPAD + kk]);
                bl[ni][1] = *reinterpret_cast<const uint32_t*>(&sWl[nr * SPAD + kk + 8]);
            }
#pragma unroll
            for (int mi = 0; mi < 2; mi++)
#pragma unroll
                for (int ni = 0; ni < 2; ni++) {
                    mma_bf16(acc[mi][ni], ah[mi], bh[ni]);
                    mma_bf16(acc[mi][ni], ah[mi], bl[ni]);
                    mma_bf16(acc[mi][ni], al[mi], bh[ni]);
                }
        }
        __syncthreads();
    }

    // ---- epilogue: bias + activation + stores ----
#pragma unroll
    for (int mi = 0; mi < 2; mi++) {
#pragma unroll
        for (int ni = 0; ni < 2; ni++) {
            const int r0 = row0 + warp_m * 32 + mi * 16 + gid;
            const int c  = col0 + warp_n * 16 + ni * 8 + tig * 2;
            const float bx = bias[c];
            const float by = bias[c + 1];
            float v0 = acc[mi][ni][0] + bx;
            float v1 = acc[mi][ni][1] + by;
            float v2 = acc[mi][ni][2] + bx;
            float v3 = acc[mi][ni][3] + by;
            if (doRelu) {
                v0 = fmaxf(v0, 0.0f); v1 = fmaxf(v1, 0.0f);
                v2 = fmaxf(v2, 0.0f); v3 = fmaxf(v3, 0.0f);
            }
            if (Cf) {
                *reinterpret_cast<float2*>(&Cf[(size_t)r0 * Nn + c])       = make_float2(v0, v1);
                *reinterpret_cast<float2*>(&Cf[(size_t)(r0 + 8) * Nn + c]) = make_float2(v2, v3);
            }
            if (Chi) {
                __nv_bfloat16 h0, l0, h1, l1;
                split_bf16(v0, h0, l0); split_bf16(v1, h1, l1);
                *reinterpret_cast<uint32_t*>(&Chi[(size_t)r0 * Nn + c]) = pack2(h0, h1);
                *reinterpret_cast<uint32_t*>(&Clo[(size_t)r0 * Nn + c]) = pack2(l0, l1);
                split_bf16(v2, h0, l0); split_bf16(v3, h1, l1);
                *reinterpret_cast<uint32_t*>(&Chi[(size_t)(r0 + 8) * Nn + c]) = pack2(h0, h1);
                *reinterpret_cast<uint32_t*>(&Clo[(size_t)(r0 + 8) * Nn + c]) = pack2(l0, l1);
            }
        }
    }
}

// ---------------- deterministic segment mean (R5 proven version) ----------------
// One block per node (grid=1024 -> high occupancy). Stage all 2048 edge ids
// in smem; 8 warps scan 256-edge chunks with ballot; cross-warp prefix gives
// globally ascending edge order (deterministic, matches reference order).
__global__ __launch_bounds__(256) void segment_kernel(const int* __restrict__ src,
                                                      const int* __restrict__ tgt) {
    __shared__ int s_ids[2 * BB];
    __shared__ int s_list[2 * BB];
    __shared__ int s_wbase[8];
    __shared__ int s_total;
    const int n   = blockIdx.x;
    const int tid = threadIdx.x;
    const int wid = tid >> 5;
    const int lid = tid & 31;

#pragma unroll
    for (int i = 0; i < 8; i++) {
        int e = tid + i * 256;
        s_ids[e] = (e < BB) ? src[e] : tgt[e - BB];
    }
    __syncthreads();

    const int chunk0 = wid * 256;

    int cnt = 0;
#pragma unroll
    for (int r = 0; r < 8; r++) {
        int e = chunk0 + r * 32 + lid;
        unsigned m = __ballot_sync(0xffffffffu, s_ids[e] == n);
        cnt += __popc(m);
    }
    if (lid == 0) s_wbase[wid] = cnt;
    __syncthreads();

    if (tid == 0) {
        int acc = 0;
#pragma unroll
        for (int w = 0; w < 8; w++) { int c = s_wbase[w]; s_wbase[w] = acc; acc += c; }
        s_total = acc;
    }
    __syncthreads();

    int base = s_wbase[wid];
#pragma unroll
    for (int r = 0; r < 8; r++) {
        int e = chunk0 + r * 32 + lid;
        bool hit = (s_ids[e] == n);
        unsigned m = __ballot_sync(0xffffffffu, hit);
        if (hit) s_list[base + __popc(m & ((1u << lid) - 1u))] = e;
        base += __popc(m);
    }
    __syncthreads();

    const int total = s_total;
    float sum = 0.0f;
    for (int i = 0; i < total; i++) {
        int e = s_list[i];
        sum += g_MSG[(size_t)e * DD + tid];
    }
    float denom = (total > 0) ? (float)total : 1.0f;
    float mean = sum / denom;
    __nv_bfloat16 h, l;
    split_bf16(mean, h, l);
    g_AGGh[(size_t)n * DD + tid] = h;
    g_AGGl[(size_t)n * DD + tid] = l;
    if (tid == 0) g_CNT[n] = total;
}

// ---------------- GRU gates + masked write ----------------
__global__ void gate_kernel(const float* __restrict__ memory,
                            float* __restrict__ out) {
    const int n = blockIdx.x;
    const int d = threadIdx.x;
    const float* gi = g_G + (size_t)n * K3;
    const float* gh = g_G + (size_t)(NN + n) * K3;

    float r  = 1.0f / (1.0f + expf(-(gi[d] + gh[d])));
    float z  = 1.0f / (1.0f + expf(-(gi[DD + d] + gh[DD + d])));
    float nn = tanhf(gi[2 * DD + d] + r * gh[2 * DD + d]);
    float h  = memory[(size_t)n * DD + d];
    float nv = (1.0f - z) * nn + z * h;
    out[(size_t)n * DD + d] = (g_CNT[n] > 0) ? nv : h;
}

// ---------------- launch ----------------
extern "C" void kernel_launch(void* const* d_in, const int* in_sizes, int n_in,
                              void* d_out, int out_size) {
    const float* memory  = (const float*)d_in[0];
    const int*   source  = (const int*)d_in[1];
    const int*   target  = (const int*)d_in[2];
    const float* dtv     = (const float*)d_in[3];
    const float* src_w1  = (const float*)d_in[4];
    const float* src_b1  = (const float*)d_in[5];
    const float* src_w2  = (const float*)d_in[6];
    const float* src_b2  = (const float*)d_in[7];
    const float* tar_w1  = (const float*)d_in[8];
    const float* tar_b1  = (const float*)d_in[9];
    const float* tar_w2  = (const float*)d_in[10];
    const float* tar_b2  = (const float*)d_in[11];
    const float* gru_wih = (const float*)d_in[12];
    const float* gru_whh = (const float*)d_in[13];
    const float* gru_bih = (const float*)d_in[14];
    const float* gru_bhh = (const float*)d_in[15];
    float* out = (float*)d_out;

    __nv_bfloat16 *pXh, *pXl, *pHh, *pHl, *pAGGh, *pAGGl;
    float *pMSG, *pG;
    cudaGetSymbolAddress((void**)&pXh, g_Xh);   cudaGetSymbolAddress((void**)&pXl, g_Xl);
    cudaGetSymbolAddress((void**)&pHh, g_Hh);   cudaGetSymbolAddress((void**)&pHl, g_Hl);
    cudaGetSymbolAddress((void**)&pAGGh, g_AGGh); cudaGetSymbolAddress((void**)&pAGGl, g_AGGl);
    cudaGetSymbolAddress((void**)&pMSG, g_MSG); cudaGetSymbolAddress((void**)&pG, g_G);

    // 1) gather concat inputs (bf16 hi/lo)
    gather_kernel<<<BB, DD>>>(memory, source, target, dtv);

    // 2) MLP layer 1 (relu): X[2048,768] -> H[2048,256] (bf16 hi/lo out)
    tgemm_kernel<<<dim3(DD / 64, (2 * BB) / 64), 256>>>(
        pXh, pXl, nullptr,
        pXh + (size_t)BB * K3, pXl + (size_t)BB * K3, nullptr,
        src_w1, tar_w1,
        src_b1, tar_b1, nullptr, pHh, pHl, BB, DD, K3, 1);

    // 3) MLP layer 2: H[2048,256] -> MSG[2048,256] fp32
    tgemm_kernel<<<dim3(DD / 64, (2 * BB) / 64), 256>>>(
        pHh, pHl, nullptr,
        pHh + (size_t)BB * DD, pHl + (size_t)BB * DD, nullptr,
        src_w2, tar_w2,
        src_b2, tar_b2, pMSG, nullptr, nullptr, BB, DD, DD, 0);

    // 4) deterministic segment mean -> AGG hi/lo, CNT (1 node/block, grid=1024)
    segment_kernel<<<NN, 256>>>(source, target);

    // 5) GRU preactivations: gi = agg@wih^T + bih ; gh = memory@whh^T + bhh
    tgemm_kernel<<<dim3(K3 / 64, (2 * NN) / 64), 256>>>(
        pAGGh, pAGGl, nullptr,
        nullptr, nullptr, memory,
        gru_wih, gru_whh,
        gru_bih, gru_bhh, pG, nullptr, nullptr, NN, K3, DD, 0);

    // 6) gates + masked output
    gate_kernel<<<NN, DD>>>(memory, out);
}